// round 1
// baseline (speedup 1.0000x reference)
#include <cuda_runtime.h>

#define FULLMASK 0xffffffffu

constexpr int BATCH   = 65536;
constexpr int WARPS   = 8;
constexpr int EPW     = 4;              // elements per warp (register blocking)
constexpr int THREADS = WARPS * 32;
constexpr int HOFF    = BATCH * 5;      // h output offset in d_out (q first, then h)

// ---------------- shared memory layout (float offsets) ----------------
constexpr int OFF_WIN  = 0;       // 3 * 8*64  = 1536   w_in0/1/2
constexpr int OFF_BIN  = 1536;    // 3 * 64    = 192
constexpr int OFF_WA   = 1728;    // 2 * 64    = 128    W @ a[:64], W @ a[64:]
constexpr int OFF_WO1  = 1856;    // 10*32     = 320
constexpr int OFF_BO1  = 2176;    // 32
constexpr int OFF_WO2  = 2208;    // 32*16     = 512
constexpr int OFF_BO2  = 2720;    // 16
constexpr int OFF_WO3  = 2736;    // 16
constexpr int OFF_BO3  = 2752;    // 1 (pad 4)
constexpr int OFF_WFC1 = 2756;    // 90*64     = 5760
constexpr int OFF_BFC1 = 8516;    // 64
constexpr int OFF_WFC2 = 8580;    // 64*5      = 320
constexpr int OFF_BFC2 = 8900;    // 5 (pad 8)
constexpr int OFF_WIH  = 8908;    // 192*65    = 12480  (row-padded to 65 -> conflict-free)
constexpr int OFF_BIH  = 21388;   // 192
constexpr int OFF_WHH  = 21580;   // 192*65    = 12480
constexpr int OFF_BHH  = 34060;   // 192 (pad to 34256)
constexpr int OFF_SCR  = 34256;

// per-element scratch layout
constexpr int SC_OBS = 0;     // 92  (obs 85 + obs_out 5)
constexpr int SC_HIN = 92;    // 64
constexpr int SC_X   = 156;   // 64
constexpr int SC_WH  = 220;   // 20  (Wh1[10], Wh2[10])
constexpr int SC_ATT = 240;   // 52  (attention 5x10)
constexpr int SC_HP1 = 292;   // 160 (5x32)
constexpr int SC_HP2 = 452;   // 80  (5x16)
constexpr int SCR_STRIDE = 536;

constexpr int SMEM_FLOATS = OFF_SCR + WARPS * EPW * SCR_STRIDE;   // 51408
constexpr int SMEM_BYTES  = SMEM_FLOATS * 4;                      // 205632 B

__device__ __forceinline__ float leakyf(float x)   { return fmaxf(x, 0.01f * x); }
__device__ __forceinline__ float sigmoidf_(float x){ return 1.0f / (1.0f + __expf(-x)); }
__device__ __forceinline__ float tanhf_(float x)   { float t = __expf(2.0f * x); return 1.0f - __fdividef(2.0f, t + 1.0f); }

__global__ __launch_bounds__(THREADS)
void atom_rnn_kernel(
    const float* __restrict__ obs,    const float* __restrict__ hidden,
    const float* __restrict__ w_in0,  const float* __restrict__ b_in0,
    const float* __restrict__ w_in1,  const float* __restrict__ b_in1,
    const float* __restrict__ w_in2,  const float* __restrict__ b_in2,
    const float* __restrict__ W,      const float* __restrict__ a,
    const float* __restrict__ w_o1,   const float* __restrict__ b_o1,
    const float* __restrict__ w_o2,   const float* __restrict__ b_o2,
    const float* __restrict__ w_o3,   const float* __restrict__ b_o3,
    const float* __restrict__ w_fc1,  const float* __restrict__ b_fc1,
    const float* __restrict__ w_ih,   const float* __restrict__ w_hh,
    const float* __restrict__ b_ih,   const float* __restrict__ b_hh,
    const float* __restrict__ w_fc2,  const float* __restrict__ b_fc2,
    float* __restrict__ out)
{
    extern __shared__ float sm[];
    const int tid = threadIdx.x;
    const int wid = tid >> 5;
    const int l   = tid & 31;

    // ---------------- cooperative weight load ----------------
    for (int i = tid; i < 512; i += THREADS) {
        sm[OFF_WIN + i]        = w_in0[i];
        sm[OFF_WIN + 512 + i]  = w_in1[i];
        sm[OFF_WIN + 1024 + i] = w_in2[i];
    }
    if (tid < 64) {
        sm[OFF_BIN + tid]       = b_in0[tid];
        sm[OFF_BIN + 64 + tid]  = b_in1[tid];
        sm[OFF_BIN + 128 + tid] = b_in2[tid];
        sm[OFF_BFC1 + tid]      = b_fc1[tid];
        // fold W @ a  (eliminates the [10,64]@[64,64] GEMM entirely)
        float a0 = 0.f, a1 = 0.f;
        for (int i = 0; i < 64; i++) {
            float w = W[i * 64 + tid];           // coalesced across tid
            a0 += w * a[i];
            a1 += w * a[64 + i];
        }
        sm[OFF_WA + tid]      = a0;
        sm[OFF_WA + 64 + tid] = a1;
    }
    for (int i = tid; i < 320; i += THREADS) { sm[OFF_WO1 + i] = w_o1[i]; sm[OFF_WFC2 + i] = w_fc2[i]; }
    for (int i = tid; i < 512; i += THREADS) { sm[OFF_WO2 + i] = w_o2[i]; }
    if (tid < 32) sm[OFF_BO1 + tid] = b_o1[tid];
    if (tid < 16) { sm[OFF_BO2 + tid] = b_o2[tid]; sm[OFF_WO3 + tid] = w_o3[tid]; }
    if (tid == 0) sm[OFF_BO3] = b_o3[0];
    if (tid < 5)  sm[OFF_BFC2 + tid] = b_fc2[tid];
    for (int i = tid; i < 5760; i += THREADS) sm[OFF_WFC1 + i] = w_fc1[i];
    for (int i = tid; i < 192 * 64; i += THREADS) {
        int g = i >> 6, c = i & 63;
        sm[OFF_WIH + g * 65 + c] = w_ih[i];
        sm[OFF_WHH + g * 65 + c] = w_hh[i];
    }
    for (int i = tid; i < 192; i += THREADS) { sm[OFF_BIH + i] = b_ih[i]; sm[OFF_BHH + i] = b_hh[i]; }
    __syncthreads();

    float* scr = sm + OFF_SCR + (wid * EPW) * SCR_STRIDE;   // this warp's 4-element arena
    const int stride = gridDim.x * WARPS * EPW;

    for (int e0 = (blockIdx.x * WARPS + wid) * EPW; e0 < BATCH; e0 += stride) {

        // ---- stage 0: load obs + hidden ----
        #pragma unroll
        for (int e = 0; e < EPW; e++) {
            const float* op = obs    + (size_t)(e0 + e) * 85;
            const float* hp = hidden + (size_t)(e0 + e) * 64;
            float* s = scr + e * SCR_STRIDE;
            for (int i = l; i < 85; i += 32) s[SC_OBS + i] = op[i];
            s[SC_HIN + l]      = hp[l];
            s[SC_HIN + 32 + l] = hp[l + 32];
        }
        __syncwarp();

        // ---- stage 1: per-token input nets -> (h_mix . Wa0, h_mix . Wa1) ----
        const float wa0l = sm[OFF_WA + l],      wa0h = sm[OFF_WA + 32 + l];
        const float wa1l = sm[OFF_WA + 64 + l], wa1h = sm[OFF_WA + 96 + l];
        #pragma unroll
        for (int t = 0; t < 10; t++) {
            const int net = (t < 5) ? 0 : ((t < 9) ? 1 : 2);
            const float* wi = sm + OFF_WIN + net * 512;
            const float* bi = sm + OFF_BIN + net * 64;
            float alo[EPW], ahi[EPW];
            #pragma unroll
            for (int e = 0; e < EPW; e++) { alo[e] = bi[l]; ahi[e] = bi[l + 32]; }
            #pragma unroll
            for (int f = 0; f < 8; f++) {
                int idx = t * 8 + f + 4; if (idx >= 80) idx -= 80;   // obs roll by 4
                const float wl = wi[f * 64 + l];
                const float wh = wi[f * 64 + 32 + l];
                #pragma unroll
                for (int e = 0; e < EPW; e++) {
                    float v = scr[e * SCR_STRIDE + SC_OBS + idx];
                    alo[e] = fmaf(v, wl, alo[e]);
                    ahi[e] = fmaf(v, wh, ahi[e]);
                }
            }
            #pragma unroll
            for (int e = 0; e < EPW; e++) {
                float hl = leakyf(alo[e]), hh = leakyf(ahi[e]);
                float p1 = hl * wa0l + hh * wa0h;
                float p2 = hl * wa1l + hh * wa1h;
                #pragma unroll
                for (int o = 16; o; o >>= 1) {
                    p1 += __shfl_xor_sync(FULLMASK, p1, o);
                    p2 += __shfl_xor_sync(FULLMASK, p2, o);
                }
                if (l == 0) {
                    scr[e * SCR_STRIDE + SC_WH + t]      = p1;
                    scr[e * SCR_STRIDE + SC_WH + 10 + t] = p2;
                }
            }
        }
        __syncwarp();

        // ---- stage 2: attention (lanes 0..9) ----
        if (l < 10) {
            #pragma unroll
            for (int e = 0; e < EPW; e++) {
                float* s = scr + e * SCR_STRIDE;
                float ev[5]; float m = -1e30f;
                if (l < 5) {
                    const float w1 = s[SC_WH + l];
                    #pragma unroll
                    for (int c = 0; c < 5; c++) {
                        float v = leakyf(w1 + s[SC_WH + 15 + c]);   // e[l][5+c]
                        ev[c] = v; m = fmaxf(m, v);
                    }
                } else {
                    const float w1 = s[SC_WH + l];                  // Wh1[5+q], l = 5+q
                    #pragma unroll
                    for (int c = 0; c < 5; c++) {
                        float v = leakyf(w1 + s[SC_WH + 10 + c]);   // e[5+q][c]
                        ev[c] = v; m = fmaxf(m, v);
                    }
                }
                float ssum = 0.f;
                #pragma unroll
                for (int c = 0; c < 5; c++) { ev[c] = __expf(ev[c] - m); ssum += ev[c]; }
                const float inv = __fdividef(1.0f, ssum);
                if (l < 5) {
                    #pragma unroll
                    for (int c = 0; c < 5; c++) s[SC_ATT + l * 10 + c] = ev[c] * inv;
                } else {
                    const int q = l - 5;
                    #pragma unroll
                    for (int c = 0; c < 5; c++) s[SC_ATT + c * 10 + 5 + q] = ev[c] * inv;
                }
            }
        }
        __syncwarp();

        // ---- stage 3: hp1 = leaky(att @ w_o1 + b_o1), 5x32, E-fused ----
        #pragma unroll
        for (int k = 0; k < 5; k++) {
            float acc[EPW];
            #pragma unroll
            for (int e = 0; e < EPW; e++) acc[e] = sm[OFF_BO1 + l];
            #pragma unroll
            for (int c = 0; c < 10; c++) {
                const float w = sm[OFF_WO1 + c * 32 + l];
                #pragma unroll
                for (int e = 0; e < EPW; e++)
                    acc[e] = fmaf(scr[e * SCR_STRIDE + SC_ATT + k * 10 + c], w, acc[e]);
            }
            #pragma unroll
            for (int e = 0; e < EPW; e++)
                scr[e * SCR_STRIDE + SC_HP1 + k * 32 + l] = leakyf(acc[e]);
        }
        __syncwarp();

        // ---- stage 4: hp2 = leaky(hp1 @ w_o2 + b_o2), 5x16, E-fused ----
        #pragma unroll
        for (int k = 0; k < 3; k++) {
            const int idx = l + 32 * k;
            const bool act = idx < 80;
            const int r = act ? (idx >> 4) : 0;
            const int o = idx & 15;
            float acc[EPW];
            #pragma unroll
            for (int e = 0; e < EPW; e++) acc[e] = sm[OFF_BO2 + o];
            #pragma unroll
            for (int c = 0; c < 32; c++) {
                const float w = sm[OFF_WO2 + c * 16 + o];
                #pragma unroll
                for (int e = 0; e < EPW; e++)
                    acc[e] = fmaf(scr[e * SCR_STRIDE + SC_HP1 + r * 32 + c], w, acc[e]);
            }
            if (act) {
                #pragma unroll
                for (int e = 0; e < EPW; e++)
                    scr[e * SCR_STRIDE + SC_HP2 + idx] = leakyf(acc[e]);
            }
        }
        __syncwarp();

        // ---- stage 5: hp3 + softmax -> obs_out appended to obs ----
        #pragma unroll
        for (int e = 0; e < EPW; e++) {
            float* s = scr + e * SCR_STRIDE;
            const int r = (l < 5) ? l : 4;
            float acc = sm[OFF_BO3];
            #pragma unroll
            for (int c = 0; c < 16; c++)
                acc = fmaf(s[SC_HP2 + r * 16 + c], sm[OFF_WO3 + c], acc);
            const float v = leakyf(acc);
            const float v0 = __shfl_sync(FULLMASK, v, 0);
            const float v1 = __shfl_sync(FULLMASK, v, 1);
            const float v2 = __shfl_sync(FULLMASK, v, 2);
            const float v3 = __shfl_sync(FULLMASK, v, 3);
            const float v4 = __shfl_sync(FULLMASK, v, 4);
            const float m  = fmaxf(fmaxf(fmaxf(v0, v1), fmaxf(v2, v3)), v4);
            const float ssum = __expf(v0 - m) + __expf(v1 - m) + __expf(v2 - m)
                             + __expf(v3 - m) + __expf(v4 - m);
            if (l < 5) s[SC_OBS + 85 + l] = __fdividef(__expf(v - m), ssum);
        }
        __syncwarp();

        // ---- stage 6: x = relu(obs_comb @ w_fc1 + b_fc1), E-fused ----
        {
            float xlo[EPW], xhi[EPW];
            #pragma unroll
            for (int e = 0; e < EPW; e++) { xlo[e] = sm[OFF_BFC1 + l]; xhi[e] = sm[OFF_BFC1 + 32 + l]; }
            #pragma unroll 6
            for (int c = 0; c < 90; c++) {
                const float wl = sm[OFF_WFC1 + c * 64 + l];
                const float wh = sm[OFF_WFC1 + c * 64 + 32 + l];
                #pragma unroll
                for (int e = 0; e < EPW; e++) {
                    const float v = scr[e * SCR_STRIDE + SC_OBS + c];
                    xlo[e] = fmaf(v, wl, xlo[e]);
                    xhi[e] = fmaf(v, wh, xhi[e]);
                }
            }
            #pragma unroll
            for (int e = 0; e < EPW; e++) {
                scr[e * SCR_STRIDE + SC_X + l]      = fmaxf(xlo[e], 0.f);
                scr[e * SCR_STRIDE + SC_X + 32 + l] = fmaxf(xhi[e], 0.f);
            }
        }
        __syncwarp();

        // ---- stage 7: GRU cell + q projection ----
        {
            float gi[2][3][EPW], gh[2][3][EPW];
            #pragma unroll
            for (int h2 = 0; h2 < 2; h2++)
                #pragma unroll
                for (int k = 0; k < 3; k++) {
                    const int g = k * 64 + l + h2 * 32;
                    #pragma unroll
                    for (int e = 0; e < EPW; e++) { gi[h2][k][e] = sm[OFF_BIH + g]; gh[h2][k][e] = sm[OFF_BHH + g]; }
                }
            #pragma unroll 4
            for (int c = 0; c < 64; c++) {
                float xv[EPW], hv[EPW];
                #pragma unroll
                for (int e = 0; e < EPW; e++) {
                    xv[e] = scr[e * SCR_STRIDE + SC_X + c];
                    hv[e] = scr[e * SCR_STRIDE + SC_HIN + c];
                }
                #pragma unroll
                for (int h2 = 0; h2 < 2; h2++)
                    #pragma unroll
                    for (int k = 0; k < 3; k++) {
                        const int g = k * 64 + l + h2 * 32;
                        const float wi2 = sm[OFF_WIH + g * 65 + c];
                        const float wh2 = sm[OFF_WHH + g * 65 + c];
                        #pragma unroll
                        for (int e = 0; e < EPW; e++) {
                            gi[h2][k][e] = fmaf(xv[e], wi2, gi[h2][k][e]);
                            gh[h2][k][e] = fmaf(hv[e], wh2, gh[h2][k][e]);
                        }
                    }
            }
            #pragma unroll
            for (int e = 0; e < EPW; e++) {
                float qp[5] = {0.f, 0.f, 0.f, 0.f, 0.f};
                #pragma unroll
                for (int h2 = 0; h2 < 2; h2++) {
                    const int j = l + h2 * 32;
                    const float rr = sigmoidf_(gi[h2][0][e] + gh[h2][0][e]);
                    const float zz = sigmoidf_(gi[h2][1][e] + gh[h2][1][e]);
                    const float nn = tanhf_(gi[h2][2][e] + rr * gh[h2][2][e]);
                    const float hprev = scr[e * SCR_STRIDE + SC_HIN + j];
                    const float hnew  = (1.0f - zz) * nn + zz * hprev;
                    out[HOFF + (size_t)(e0 + e) * 64 + j] = hnew;
                    #pragma unroll
                    for (int k = 0; k < 5; k++)
                        qp[k] = fmaf(hnew, sm[OFF_WFC2 + j * 5 + k], qp[k]);
                }
                #pragma unroll
                for (int k = 0; k < 5; k++)
                    #pragma unroll
                    for (int o = 16; o; o >>= 1)
                        qp[k] += __shfl_xor_sync(FULLMASK, qp[k], o);
                if (l == 0) {
                    #pragma unroll
                    for (int k = 0; k < 5; k++)
                        out[(size_t)(e0 + e) * 5 + k] = qp[k] + sm[OFF_BFC2 + k];
                }
            }
        }
        __syncwarp();
    }
}

extern "C" void kernel_launch(void* const* d_in, const int* in_sizes, int n_in,
                              void* d_out, int out_size) {
    (void)in_sizes; (void)n_in; (void)out_size;
    int dev = 0;
    cudaGetDevice(&dev);
    int nsm = 148;
    cudaDeviceGetAttribute(&nsm, cudaDevAttrMultiProcessorCount, dev);
    cudaFuncSetAttribute(atom_rnn_kernel, cudaFuncAttributeMaxDynamicSharedMemorySize, SMEM_BYTES);
    atom_rnn_kernel<<<nsm, THREADS, SMEM_BYTES>>>(
        (const float*)d_in[0],  (const float*)d_in[1],
        (const float*)d_in[2],  (const float*)d_in[3],
        (const float*)d_in[4],  (const float*)d_in[5],
        (const float*)d_in[6],  (const float*)d_in[7],
        (const float*)d_in[8],  (const float*)d_in[9],
        (const float*)d_in[10], (const float*)d_in[11],
        (const float*)d_in[12], (const float*)d_in[13],
        (const float*)d_in[14], (const float*)d_in[15],
        (const float*)d_in[16], (const float*)d_in[17],
        (const float*)d_in[18], (const float*)d_in[19],
        (const float*)d_in[20], (const float*)d_in[21],
        (const float*)d_in[22], (const float*)d_in[23],
        (float*)d_out);
}